// round 3
// baseline (speedup 1.0000x reference)
#include <cuda_runtime.h>

// Problem constants
static constexpr int Bc = 2048;
static constexpr int Tc = 128;
static constexpr int Ec = 192;
static constexpr int Hc = 192;
static constexpr float SCALE_F = 0.07216878364870322f; // 192^-0.5

// Scratch for Q, K, V (static device arrays: allowed; no cudaMalloc)
__device__ __align__(16) float g_q[(long long)Bc * Tc * Hc];
__device__ __align__(16) float g_k[(long long)Bc * Tc * Hc];
__device__ __align__(16) float g_v[(long long)Bc * Tc * Hc];

// ---------------------------------------------------------------------------
// Kernel 1: QKV projection.  One block per batch b.
//   out[b,t,h] = sum_e x[b,t,e] * W[h,e]   for W in {Wq, Wk, Wv}
// x tile (128x192) staged in smem transposed As[e][t] (odd stride -> no
// 32-way transpose-store conflicts).  Per (matrix, n-tile) a 128x96 output
// tile is computed with 8x6 register micro-tiles.  Bs is double-buffered so
// the next W k-tile's global loads overlap the current FMA burst and only
// one __syncthreads() per k-iteration is needed.
// ---------------------------------------------------------------------------
static constexpr int AS_S = 129;              // odd stride for As
static constexpr int BS_S = 100;              // padded stride for Bs
static constexpr int SMEM1 = (Ec * AS_S + 2 * 16 * BS_S) * 4;

__global__ __launch_bounds__(256, 2) void qkv_kernel(
    const float* __restrict__ x,
    const float* __restrict__ Wq,
    const float* __restrict__ Wk,
    const float* __restrict__ Wv)
{
    extern __shared__ float sm1[];
    float* As = sm1;                       // [192][AS_S]  As[e*AS_S + t]
    float* Bs0 = sm1 + Ec * AS_S;          // [16][BS_S] ping
    float* Bs1 = Bs0 + 16 * BS_S;          // [16][BS_S] pong

    const int b   = blockIdx.x;
    const int tid = threadIdx.x;
    const int ty  = tid >> 4;        // 0..15 -> rows ty*8 .. ty*8+7
    const int tx  = tid & 15;        // 0..15 -> cols tx*6 .. tx*6+5

    const float* xb = x + (long long)b * (Tc * Ec);

    // Stage x[b] transposed into As.  24576 floats = 6144 float4 / 256 thr.
    #pragma unroll
    for (int i = 0; i < 24; i++) {
        int lin = (tid + i * 256) * 4;
        int t = lin / Ec;
        int e = lin % Ec;            // multiple of 4, rows are 192 floats
        float4 v = *reinterpret_cast<const float4*>(xb + lin);
        As[(e + 0) * AS_S + t] = v.x;
        As[(e + 1) * AS_S + t] = v.y;
        As[(e + 2) * AS_S + t] = v.z;
        As[(e + 3) * AS_S + t] = v.w;
    }

    const float* Ws[3] = {Wq, Wk, Wv};
    float*       Os[3] = {g_q, g_k, g_v};

    // Helper lambda: load a 96x16 W tile (rows n0.., k cols k0..k0+15) into Bsd.
    auto load_Bs = [&](float* Bsd, const float* W, int n0, int k0) {
        // 1536 floats = 384 float4, 256 threads -> iterations 0 and (tid<128).
        #pragma unroll
        for (int i = 0; i < 2; i++) {
            int idx = tid + i * 256;
            if (idx < 384) {
                int lin = idx * 4;
                int n  = lin >> 4;      // 0..95
                int kk = lin & 15;      // 0,4,8,12
                float4 v = *reinterpret_cast<const float4*>(
                    W + (long long)(n0 + n) * Ec + k0 + kk);
                Bsd[(kk + 0) * BS_S + n] = v.x;
                Bsd[(kk + 1) * BS_S + n] = v.y;
                Bsd[(kk + 2) * BS_S + n] = v.z;
                Bsd[(kk + 3) * BS_S + n] = v.w;
            }
        }
    };

    for (int w = 0; w < 3; w++) {
        const float* W = Ws[w];
        float* outp = Os[w] + (long long)b * (Tc * Hc);

        for (int nt = 0; nt < 2; nt++) {
            const int n0 = nt * 96;
            float acc[8][6];
            #pragma unroll
            for (int i = 0; i < 8; i++)
                #pragma unroll
                for (int j = 0; j < 6; j++) acc[i][j] = 0.0f;

            // Prologue: fill ping buffer (also waits for As on first pass /
            // protects pong reuse from previous tile).
            __syncthreads();
            load_Bs(Bs0, W, n0, 0);
            __syncthreads();

            #pragma unroll
            for (int kt = 0; kt < 12; kt++) {          // 12 k-tiles of 16
                const int k0 = kt * 16;
                float* Bcur = (kt & 1) ? Bs1 : Bs0;
                float* Bnxt = (kt & 1) ? Bs0 : Bs1;

                if (kt < 11)
                    load_Bs(Bnxt, W, n0, k0 + 16);     // overlap with FMAs

                #pragma unroll
                for (int kk = 0; kk < 16; kk++) {
                    float a[8], bb[6];
                    #pragma unroll
                    for (int i = 0; i < 8; i++)
                        a[i] = As[(k0 + kk) * AS_S + ty * 8 + i];
                    #pragma unroll
                    for (int j = 0; j < 6; j++)
                        bb[j] = Bcur[kk * BS_S + tx * 6 + j];
                    #pragma unroll
                    for (int i = 0; i < 8; i++)
                        #pragma unroll
                        for (int j = 0; j < 6; j++)
                            acc[i][j] = fmaf(a[i], bb[j], acc[i][j]);
                }
                __syncthreads();   // Bnxt stores done by all before next read
            }

            #pragma unroll
            for (int i = 0; i < 8; i++)
                #pragma unroll
                for (int j = 0; j < 6; j++)
                    outp[(ty * 8 + i) * Hc + n0 + tx * 6 + j] = acc[i][j];
        }
    }
}

// ---------------------------------------------------------------------------
// Kernel 2: causal attention.  One block per batch.
// K staged transposed Kt[h][t] (odd stride), V staged [t][h].
// Each warp owns 16 query rows, processed 4 at a time; the causal number of
// 32-wide key blocks is specialized via template NJ.
// ---------------------------------------------------------------------------
static constexpr int KT_S = 129;
static constexpr int SMEM2 = (Ec * KT_S + Tc * Hc + 8 * 4 * Tc) * 4;

template <int NJ>
__device__ __forceinline__ void score_accum(
    const float* __restrict__ Qg, int q0,
    const float* __restrict__ Kt, int lane, float s[4][4])
{
    #pragma unroll 2
    for (int e0 = 0; e0 < Ec; e0 += 4) {
        float4 q4[4];
        #pragma unroll
        for (int r = 0; r < 4; r++)
            q4[r] = __ldg(reinterpret_cast<const float4*>(
                Qg + (q0 + r) * Hc + e0));
        const float* qp = reinterpret_cast<const float*>(q4);
        #pragma unroll
        for (int ee = 0; ee < 4; ee++) {
            float kv[NJ];
            #pragma unroll
            for (int j = 0; j < NJ; j++)
                kv[j] = Kt[(e0 + ee) * KT_S + lane + 32 * j];
            #pragma unroll
            for (int r = 0; r < 4; r++) {
                float qe = qp[r * 4 + ee];
                #pragma unroll
                for (int j = 0; j < NJ; j++)
                    s[r][j] = fmaf(qe, kv[j], s[r][j]);
            }
        }
    }
}

__global__ __launch_bounds__(256, 1) void attn_kernel(float* __restrict__ out)
{
    extern __shared__ float sm2[];
    float* Kt  = sm2;                    // [192][KT_S]
    float* Vs  = sm2 + Ec * KT_S;        // [128][192]
    float* Wei = Vs + Tc * Hc;           // [8 warps][4 rows][128]

    const int b    = blockIdx.x;
    const int tid  = threadIdx.x;
    const int warp = tid >> 5;
    const int lane = tid & 31;

    const float* Qg = g_q + (long long)b * Tc * Hc;
    const float* Kg = g_k + (long long)b * Tc * Hc;
    const float* Vg = g_v + (long long)b * Tc * Hc;
    float*       ob = out + (long long)b * Tc * Hc;

    // Stage K (transposed) and V.
    #pragma unroll
    for (int i = 0; i < 24; i++) {
        int lin = (tid + i * 256) * 4;
        int t = lin / Ec;
        int e = lin % Ec;
        float4 v = *reinterpret_cast<const float4*>(Kg + lin);
        Kt[(e + 0) * KT_S + t] = v.x;
        Kt[(e + 1) * KT_S + t] = v.y;
        Kt[(e + 2) * KT_S + t] = v.z;
        Kt[(e + 3) * KT_S + t] = v.w;
        reinterpret_cast<float4*>(Vs)[tid + i * 256] =
            reinterpret_cast<const float4*>(Vg)[tid + i * 256];
    }
    __syncthreads();

    float* wei = Wei + warp * (4 * Tc);

    for (int g = 0; g < 4; g++) {
        const int q0 = warp * 16 + g * 4;          // rows q0..q0+3
        const int nj = (q0 + 3) / 32 + 1;          // causal 32-key blocks

        float s[4][4];
        #pragma unroll
        for (int r = 0; r < 4; r++)
            #pragma unroll
            for (int j = 0; j < 4; j++) s[r][j] = 0.0f;

        switch (nj) {
            case 1:  score_accum<1>(Qg, q0, Kt, lane, s); break;
            case 2:  score_accum<2>(Qg, q0, Kt, lane, s); break;
            case 3:  score_accum<3>(Qg, q0, Kt, lane, s); break;
            default: score_accum<4>(Qg, q0, Kt, lane, s); break;
        }

        // Softmax per row (warp holds the whole 128-wide row: k = lane+32j)
        #pragma unroll
        for (int r = 0; r < 4; r++) {
            const int q = q0 + r;
            float v0[4];
            #pragma unroll
            for (int j = 0; j < 4; j++) {
                int k = lane + 32 * j;
                v0[j] = (k <= q) ? s[r][j] * SCALE_F : -1e30f;
            }
            float m = fmaxf(fmaxf(v0[0], v0[1]), fmaxf(v0[2], v0[3]));
            #pragma unroll
            for (int off = 16; off > 0; off >>= 1)
                m = fmaxf(m, __shfl_xor_sync(0xffffffffu, m, off));
            float p[4], sum = 0.0f;
            #pragma unroll
            for (int j = 0; j < 4; j++) { p[j] = __expf(v0[j] - m); sum += p[j]; }
            #pragma unroll
            for (int off = 16; off > 0; off >>= 1)
                sum += __shfl_xor_sync(0xffffffffu, sum, off);
            float inv = 1.0f / sum;
            #pragma unroll
            for (int j = 0; j < 4; j++)
                wei[r * Tc + lane + 32 * j] = p[j] * inv;  // masked -> exactly 0
        }
        __syncwarp();

        // P @ V for the 4 rows; causal loop bound (extra k have weight 0).
        float o[4][6];
        #pragma unroll
        for (int r = 0; r < 4; r++)
            #pragma unroll
            for (int j = 0; j < 6; j++) o[r][j] = 0.0f;

        for (int k0 = 0; k0 < q0 + 4; k0 += 4) {
            float4 w4[4];
            #pragma unroll
            for (int r = 0; r < 4; r++)
                w4[r] = *reinterpret_cast<const float4*>(wei + r * Tc + k0);
            const float* wp = reinterpret_cast<const float*>(w4);
            #pragma unroll
            for (int kk = 0; kk < 4; kk++) {
                float vv[6];
                #pragma unroll
                for (int j = 0; j < 6; j++)
                    vv[j] = Vs[(k0 + kk) * Hc + lane + 32 * j];
                #pragma unroll
                for (int r = 0; r < 4; r++) {
                    float wr = wp[r * 4 + kk];
                    #pragma unroll
                    for (int j = 0; j < 6; j++)
                        o[r][j] = fmaf(wr, vv[j], o[r][j]);
                }
            }
        }

        #pragma unroll
        for (int r = 0; r < 4; r++)
            #pragma unroll
            for (int j = 0; j < 6; j++)
                ob[(q0 + r) * Hc + lane + 32 * j] = o[r][j];
        __syncwarp();   // wei reused next group
    }
}

// ---------------------------------------------------------------------------
extern "C" void kernel_launch(void* const* d_in, const int* in_sizes, int n_in,
                              void* d_out, int out_size)
{
    const float* x  = (const float*)d_in[0];
    const float* Wq = (const float*)d_in[1];
    const float* Wk = (const float*)d_in[2];
    const float* Wv = (const float*)d_in[3];
    float* out = (float*)d_out;

    cudaFuncSetAttribute((const void*)qkv_kernel,
                         cudaFuncAttributeMaxDynamicSharedMemorySize, SMEM1);
    cudaFuncSetAttribute((const void*)attn_kernel,
                         cudaFuncAttributeMaxDynamicSharedMemorySize, SMEM2);

    qkv_kernel<<<Bc, 256, SMEM1>>>(x, Wq, Wk, Wv);
    attn_kernel<<<Bc, 256, SMEM2>>>(out);
}

// round 6
// speedup vs baseline: 1.9472x; 1.9472x over previous
#include <cuda_runtime.h>

// Problem constants
static constexpr int Bc = 2048;
static constexpr int Tc = 128;
static constexpr int Ec = 192;
static constexpr int Hc = 192;
static constexpr float SCALE_F = 0.07216878364870322f; // 192^-0.5

// Scratch for Q, K, V
__device__ __align__(16) float g_q[(long long)Bc * Tc * Hc];
__device__ __align__(16) float g_k[(long long)Bc * Tc * Hc];
__device__ __align__(16) float g_v[(long long)Bc * Tc * Hc];

// ---------------------------------------------------------------------------
// TF32 helpers
// ---------------------------------------------------------------------------
__device__ __forceinline__ unsigned f2tf(float f) {
    unsigned u;
    asm("cvt.rna.tf32.f32 %0, %1;" : "=r"(u) : "f"(f));
    return u;
}

__device__ __forceinline__ void mma_tf32(float d[4], const unsigned a[4],
                                         const unsigned b[2]) {
    asm volatile(
        "mma.sync.aligned.m16n8k8.row.col.f32.tf32.tf32.f32 "
        "{%0,%1,%2,%3}, {%4,%5,%6,%7}, {%8,%9}, {%0,%1,%2,%3};\n"
        : "+f"(d[0]), "+f"(d[1]), "+f"(d[2]), "+f"(d[3])
        : "r"(a[0]), "r"(a[1]), "r"(a[2]), "r"(a[3]), "r"(b[0]), "r"(b[1]));
}

// ---------------------------------------------------------------------------
// Kernel 1: QKV projection with TF32 tensor-core mma.
// One CTA per batch.  out[t,h] = sum_e x[t,e] * W[h,e].
// A = x (m=t, k=e) row-major in smem, stride ES=196 (=4 mod 32 -> the
// (group,tig) fragment read pattern hits all 32 banks).
// B tile Bs[k][n] = W[n0+n][k0+k], 16 k x 96 n per stage, stride 104
// (=8 mod 32 -> conflict-free b-fragment reads), double-buffered.
// Warps: 4(m) x 2(n) grid; warp tile 32m x 48n = 2 x 6 mma atoms.
// n processed in 2 halves of 96 to keep accumulators at 48 regs.
// ---------------------------------------------------------------------------
static constexpr int ES   = 196;   // As row stride (floats)
static constexpr int BSN  = 104;   // Bs row stride (floats)
static constexpr int KC   = 16;    // k-chunk per stage
static constexpr int SMEM1 = (Tc * ES + 2 * KC * BSN) * 4;

__global__ __launch_bounds__(256, 2) void qkv_kernel(
    const float* __restrict__ x,
    const float* __restrict__ Wq,
    const float* __restrict__ Wk,
    const float* __restrict__ Wv)
{
    extern __shared__ unsigned sm1[];
    unsigned* As  = sm1;                   // [128][ES] tf32 bits
    unsigned* Bs0 = sm1 + Tc * ES;         // [KC][BSN]
    unsigned* Bs1 = Bs0 + KC * BSN;

    const int b    = blockIdx.x;
    const int tid  = threadIdx.x;
    const int warp = tid >> 5;
    const int lane = tid & 31;
    const int g    = lane >> 2;            // 0..7
    const int tig  = lane & 3;             // 0..3
    const int m0   = (warp >> 1) * 32;     // warp m origin
    const int wn   = warp & 1;             // warp n within 96-half

    const float* xb = x + (long long)b * (Tc * Ec);

    // Stage x (cvt to tf32) into As.  24576 floats = 6144 float4 / 256 thr.
    #pragma unroll
    for (int i = 0; i < 24; i++) {
        int lin = (tid + i * 256) * 4;
        int t = lin / Ec;
        int e = lin % Ec;
        float4 v = *reinterpret_cast<const float4*>(xb + lin);
        uint4 u = make_uint4(f2tf(v.x), f2tf(v.y), f2tf(v.z), f2tf(v.w));
        *reinterpret_cast<uint4*>(&As[t * ES + e]) = u;
    }

    // Stage one 96n x 16k W tile: Bs[k][n] = W[n0+n][k0+k].
    auto load_Bs = [&](unsigned* dst, const float* W, int n0, int k0) {
        #pragma unroll
        for (int i = 0; i < 2; i++) {
            int idx = tid + i * 256;
            if (idx < 384) {
                int n  = idx >> 2;          // 0..95
                int kk = (idx & 3) * 4;     // 0,4,8,12
                float4 v = *reinterpret_cast<const float4*>(
                    W + (long long)(n0 + n) * Ec + k0 + kk);
                dst[(kk + 0) * BSN + n] = f2tf(v.x);
                dst[(kk + 1) * BSN + n] = f2tf(v.y);
                dst[(kk + 2) * BSN + n] = f2tf(v.z);
                dst[(kk + 3) * BSN + n] = f2tf(v.w);
            }
        }
    };

    const float* Ws[3] = {Wq, Wk, Wv};
    float*       Os[3] = {g_q, g_k, g_v};

    for (int w = 0; w < 3; w++) {
        const float* W = Ws[w];
        float* outp = Os[w] + (long long)b * (Tc * Hc);

        for (int nh = 0; nh < 2; nh++) {
            const int n0 = nh * 96;
            float acc[2][6][4];
            #pragma unroll
            for (int ma = 0; ma < 2; ma++)
                #pragma unroll
                for (int na = 0; na < 6; na++)
                    #pragma unroll
                    for (int r = 0; r < 4; r++) acc[ma][na][r] = 0.0f;

            __syncthreads();              // buffers free (also orders As once)
            load_Bs(Bs0, W, n0, 0);
            __syncthreads();

            #pragma unroll
            for (int kc = 0; kc < 12; kc++) {        // 12 chunks of 16
                unsigned* Bcur = (kc & 1) ? Bs1 : Bs0;
                unsigned* Bnxt = (kc & 1) ? Bs0 : Bs1;
                if (kc < 11) load_Bs(Bnxt, W, n0, kc * 16 + 16);

                #pragma unroll
                for (int ks = 0; ks < 2; ks++) {     // two k=8 steps
                    const int k0g = kc * 16 + ks * 8; // global k for A
                    const int k0l = ks * 8;           // local k in Bs

                    unsigned a[2][4];
                    #pragma unroll
                    for (int ma = 0; ma < 2; ma++) {
                        const int rb = m0 + ma * 16;
                        a[ma][0] = As[(rb + g    ) * ES + k0g + tig    ];
                        a[ma][1] = As[(rb + g + 8) * ES + k0g + tig    ];
                        a[ma][2] = As[(rb + g    ) * ES + k0g + tig + 4];
                        a[ma][3] = As[(rb + g + 8) * ES + k0g + tig + 4];
                    }
                    #pragma unroll
                    for (int na = 0; na < 6; na++) {
                        unsigned bb[2];
                        const int nn = wn * 48 + na * 8 + g;
                        bb[0] = Bcur[(k0l + tig    ) * BSN + nn];
                        bb[1] = Bcur[(k0l + tig + 4) * BSN + nn];
                        mma_tf32(acc[0][na], a[0], bb);
                        mma_tf32(acc[1][na], a[1], bb);
                    }
                }
                __syncthreads();
            }

            // Epilogue: c0,c1 at (row=g, col=2*tig,+1); c2,c3 at row=g+8.
            #pragma unroll
            for (int ma = 0; ma < 2; ma++) {
                const int rb = m0 + ma * 16 + g;
                #pragma unroll
                for (int na = 0; na < 6; na++) {
                    const int cb = n0 + wn * 48 + na * 8 + 2 * tig;
                    *reinterpret_cast<float2*>(&outp[rb * Hc + cb]) =
                        make_float2(acc[ma][na][0], acc[ma][na][1]);
                    *reinterpret_cast<float2*>(&outp[(rb + 8) * Hc + cb]) =
                        make_float2(acc[ma][na][2], acc[ma][na][3]);
                }
            }
        }
    }
}

// ---------------------------------------------------------------------------
// Kernel 2: causal attention.  One CTA (512 thr, 16 warps) per batch.
// K staged transposed Kt[h][t] (stride 128; score reads are stride-1 across
// lanes so conflict-free), V staged [t][h].  Each warp owns 8 query rows,
// processed 4 at a time; causal 32-key block count specialized via template.
// ---------------------------------------------------------------------------
static constexpr int KT_S = 128;
static constexpr int SMEM2 = (Ec * KT_S + Tc * Hc + 16 * 4 * Tc) * 4;

template <int NJ>
__device__ __forceinline__ void score_accum(
    const float* __restrict__ Qg, int q0,
    const float* __restrict__ Kt, int lane, float s[4][4])
{
    #pragma unroll 2
    for (int e0 = 0; e0 < Ec; e0 += 4) {
        float4 q4[4];
        #pragma unroll
        for (int r = 0; r < 4; r++)
            q4[r] = __ldg(reinterpret_cast<const float4*>(
                Qg + (q0 + r) * Hc + e0));
        const float* qp = reinterpret_cast<const float*>(q4);
        #pragma unroll
        for (int ee = 0; ee < 4; ee++) {
            float kv[NJ];
            #pragma unroll
            for (int j = 0; j < NJ; j++)
                kv[j] = Kt[(e0 + ee) * KT_S + lane + 32 * j];
            #pragma unroll
            for (int r = 0; r < 4; r++) {
                float qe = qp[r * 4 + ee];
                #pragma unroll
                for (int j = 0; j < NJ; j++)
                    s[r][j] = fmaf(qe, kv[j], s[r][j]);
            }
        }
    }
}

__global__ __launch_bounds__(512, 1) void attn_kernel(float* __restrict__ out)
{
    extern __shared__ float sm2[];
    float* Kt  = sm2;                    // [192][128]
    float* Vs  = sm2 + Ec * KT_S;        // [128][192]
    float* Wei = Vs + Tc * Hc;           // [16 warps][4 rows][128]

    const int b    = blockIdx.x;
    const int tid  = threadIdx.x;
    const int warp = tid >> 5;
    const int lane = tid & 31;

    const float* Qg = g_q + (long long)b * Tc * Hc;
    const float* Kg = g_k + (long long)b * Tc * Hc;
    const float* Vg = g_v + (long long)b * Tc * Hc;
    float*       ob = out + (long long)b * Tc * Hc;

    // Stage K (transposed) and V.  6144 float4 / 512 thr = 12 iters.
    #pragma unroll
    for (int i = 0; i < 12; i++) {
        int lin = (tid + i * 512) * 4;
        int t = lin / Ec;
        int e = lin % Ec;
        float4 v = *reinterpret_cast<const float4*>(Kg + lin);
        Kt[(e + 0) * KT_S + t] = v.x;
        Kt[(e + 1) * KT_S + t] = v.y;
        Kt[(e + 2) * KT_S + t] = v.z;
        Kt[(e + 3) * KT_S + t] = v.w;
        reinterpret_cast<float4*>(Vs)[tid + i * 512] =
            reinterpret_cast<const float4*>(Vg)[tid + i * 512];
    }
    __syncthreads();

    float* wei = Wei + warp * (4 * Tc);

    #pragma unroll
    for (int g = 0; g < 2; g++) {
        const int q0 = warp * 8 + g * 4;           // rows q0..q0+3
        const int nj = (q0 + 3) / 32 + 1;          // causal 32-key blocks

        float s[4][4];
        #pragma unroll
        for (int r = 0; r < 4; r++)
            #pragma unroll
            for (int j = 0; j < 4; j++) s[r][j] = 0.0f;

        switch (nj) {
            case 1:  score_accum<1>(Qg, q0, Kt, lane, s); break;
            case 2:  score_accum<2>(Qg, q0, Kt, lane, s); break;
            case 3:  score_accum<3>(Qg, q0, Kt, lane, s); break;
            default: score_accum<4>(Qg, q0, Kt, lane, s); break;
        }

        // Softmax per row (warp holds whole 128-wide row: k = lane+32j)
        #pragma unroll
        for (int r = 0; r < 4; r++) {
            const int q = q0 + r;
            float v0[4];
            #pragma unroll
            for (int j = 0; j < 4; j++) {
                int k = lane + 32 * j;
                v0[j] = (k <= q) ? s[r][j] * SCALE_F : -1e30f;
            }
            float m = fmaxf(fmaxf(v0[0], v0[1]), fmaxf(v0[2], v0[3]));
            #pragma unroll
            for (int off = 16; off > 0; off >>= 1)
                m = fmaxf(m, __shfl_xor_sync(0xffffffffu, m, off));
            float p[4], sum = 0.0f;
            #pragma unroll
            for (int j = 0; j < 4; j++) { p[j] = __expf(v0[j] - m); sum += p[j]; }
            #pragma unroll
            for (int off = 16; off > 0; off >>= 1)
                sum += __shfl_xor_sync(0xffffffffu, sum, off);
            float inv = 1.0f / sum;
            #pragma unroll
            for (int j = 0; j < 4; j++)
                wei[r * Tc + lane + 32 * j] = p[j] * inv;  // masked -> 0
        }
        __syncwarp();

        // P @ V; causal loop bound (extra k have weight exactly 0).
        float o[4][6];
        #pragma unroll
        for (int r = 0; r < 4; r++)
            #pragma unroll
            for (int j = 0; j < 6; j++) o[r][j] = 0.0f;

        for (int k0 = 0; k0 < q0 + 4; k0 += 4) {
            float4 w4[4];
            #pragma unroll
            for (int r = 0; r < 4; r++)
                w4[r] = *reinterpret_cast<const float4*>(wei + r * Tc + k0);
            const float* wp = reinterpret_cast<const float*>(w4);
            #pragma unroll
            for (int kk = 0; kk < 4; kk++) {
                float vv[6];
                #pragma unroll
                for (int j = 0; j < 6; j++)
                    vv[j] = Vs[(k0 + kk) * Hc + lane + 32 * j];
                #pragma unroll
                for (int r = 0; r < 4; r++) {
                    float wr = wp[r * 4 + kk];
                    #pragma unroll
                    for (int j = 0; j < 6; j++)
                        o[r][j] = fmaf(wr, vv[j], o[r][j]);
                }
            }
        }

        #pragma unroll
        for (int r = 0; r < 4; r++)
            #pragma unroll
            for (int j = 0; j < 6; j++)
                ob[(q0 + r) * Hc + lane + 32 * j] = o[r][j];
        __syncwarp();   // wei reused next group
    }
}

// ---------------------------------------------------------------------------
extern "C" void kernel_launch(void* const* d_in, const int* in_sizes, int n_in,
                              void* d_out, int out_size)
{
    const float* x  = (const float*)d_in[0];
    const float* Wq = (const float*)d_in[1];
    const float* Wk = (const float*)d_in[2];
    const float* Wv = (const float*)d_in[3];
    float* out = (float*)d_out;

    cudaFuncSetAttribute((const void*)qkv_kernel,
                         cudaFuncAttributeMaxDynamicSharedMemorySize, SMEM1);
    cudaFuncSetAttribute((const void*)attn_kernel,
                         cudaFuncAttributeMaxDynamicSharedMemorySize, SMEM2);

    qkv_kernel<<<Bc, 256, SMEM1>>>(x, Wq, Wk, Wv);
    attn_kernel<<<Bc, 512, SMEM2>>>(out);
}